// round 12
// baseline (speedup 1.0000x reference)
#include <cuda_runtime.h>

// Problem constants
#define NPG   61
#define NB    128
#define NNODE 7808         // NB*NPG
#define NE    468480       // NB * 61*60
#define EPG   3660
#define LQ    160
#define NF    64
#define HC    128

typedef unsigned long long ull;

// ---------------- f32x2 helpers ----------------
__device__ __forceinline__ ull pack2(float lo, float hi) {
    ull r; asm("mov.b64 %0, {%1, %2};" : "=l"(r) : "f"(lo), "f"(hi)); return r;
}
__device__ __forceinline__ float2 u2f(ull u) {
    float2 v; asm("mov.b64 {%0, %1}, %2;" : "=f"(v.x), "=f"(v.y) : "l"(u)); return v;
}
__device__ __forceinline__ ull fma2(ull a, ull b, ull c) {
    ull d; asm("fma.rn.f32x2 %0, %1, %2, %3;" : "=l"(d) : "l"(a), "l"(b), "l"(c)); return d;
}

// ---------------- device scratch ----------------
__device__ float      d_At[NB * 64 * 64];     // TRANSPOSED adjacency At[g][s][d]
__device__ ulonglong2 d_w1q[64 * 3 * 64];     // conv1 weights tap-paired: [(c*3+kp)*64+f]
__device__ float      d_w2t[64 * 3 * 64];     // conv2 weights transposed
__device__ ulonglong2 d_gw0u[16 * HC];
__device__ ulonglong2 d_gw1u[32 * HC];
__device__ ulonglong2 d_gw2u[32 * HC];
__device__ float      d_H0[NNODE * NF];
__device__ float      d_G1[NNODE * HC];
__device__ float      d_G2[NNODE * HC];
__device__ float      d_HW[NNODE * HC];
__device__ float      d_P[NB * NPG * HC];     // lin0 partials, [g][node][j]
__device__ float      d_bp1s[61 * NF], d_bp1q[61 * NF];
__device__ float      d_bp2s[2 * NB * HC], d_bp2q[2 * NB * HC];
__device__ float      d_sc1[NF], d_sh1[NF];
__device__ float      d_sc2[HC], d_sh2[HC];

// ---------------- K0a: zero adjacency ----------------
__global__ void k_prep_zero() {
    int t0 = blockIdx.x * blockDim.x + threadIdx.x;
    int stride = gridDim.x * blockDim.x;
    for (int i = t0; i < NB * 64 * 64; i += stride) d_At[i] = 0.f;
}

// ---------------- K0b: transpose/pack weights ----------------
__global__ void k_prep_w(const float* __restrict__ w1, const float* __restrict__ w2,
                         const float* __restrict__ gw0, const float* __restrict__ gw1,
                         const float* __restrict__ gw2) {
    int t0 = blockIdx.x * blockDim.x + threadIdx.x;
    int stride = gridDim.x * blockDim.x;
    // conv1 tap pairs: kp=0 -> taps(0,1), kp=1 -> taps(2,3), kp=2 -> (tap4, tap4)
    for (int i = t0; i < 64 * 3 * 64; i += stride) {
        int f = i & 63; int r = i >> 6; int kp = r % 3; int c = r / 3;
        int k0 = 2 * kp, k1 = (kp == 2) ? 4 : (2 * kp + 1);
        float va = w1[(f * 64 + c) * 5 + k0];
        float vb = w1[(f * 64 + c) * 5 + k1];
        ulonglong2 u;
        u.x = pack2(va, va);
        u.y = pack2(vb, vb);
        d_w1q[i] = u;
    }
    for (int i = t0; i < 64 * 3 * 64; i += stride) {
        int f = i & 63; int r = i >> 6; int k = r % 3; int c = r / 3;
        d_w2t[i] = w2[(f * 64 + c) * 3 + k];
    }
    for (int i = t0; i < 16 * HC; i += stride) {
        int j = i & (HC - 1); int kq = i >> 7;
        ulonglong2 u;
        u.x = pack2(gw0[(4 * kq) * HC + j], gw0[(4 * kq + 1) * HC + j]);
        u.y = pack2(gw0[(4 * kq + 2) * HC + j], gw0[(4 * kq + 3) * HC + j]);
        d_gw0u[i] = u;
    }
    for (int i = t0; i < 32 * HC; i += stride) {
        int j = i & (HC - 1); int kq = i >> 7;
        ulonglong2 u, v;
        u.x = pack2(gw1[(4 * kq) * HC + j], gw1[(4 * kq + 1) * HC + j]);
        u.y = pack2(gw1[(4 * kq + 2) * HC + j], gw1[(4 * kq + 3) * HC + j]);
        d_gw1u[i] = u;
        v.x = pack2(gw2[(4 * kq) * HC + j], gw2[(4 * kq + 1) * HC + j]);
        v.y = pack2(gw2[(4 * kq + 2) * HC + j], gw2[(4 * kq + 3) * HC + j]);
        d_gw2u[i] = v;
    }
}

// ---------------- K1: edges ----------------
__global__ void __launch_bounds__(1024) k_edges(
        const float* __restrict__ ef, const int* __restrict__ ei,
        const float* __restrict__ eww, const float* __restrict__ ewb,
        float* __restrict__ out) {
    int w = threadIdx.x >> 5;
    int l = threadIdx.x & 31;
    int i0 = blockIdx.x * 32;
    int g0 = blockIdx.y * 32;
    __shared__ float ts[32][33];

    int g = g0 + w;
    int i = i0 + l;
    float v = 0.f;
    if (i < EPG) {
        int e = g * EPG + i;
        v = tanhf(fmaf(ef[e * 3 + 0], eww[0],
                 fmaf(ef[e * 3 + 1], eww[1],
                 fmaf(ef[e * 3 + 2], eww[2], ewb[0]))));
        int s = ei[e];
        int d = ei[NE + e];
        int g2 = d / NPG;
        int dl = d - g2 * NPG;
        int sl = s - g2 * NPG;
        d_At[(g2 * 64 + sl) * 64 + dl] = v;
    }
    ts[w][l] = v;
    __syncthreads();
    int iw = i0 + w;
    if (iw < EPG) out[NB * 4 + iw * NB + g0 + l] = ts[l][w];
}

// ---------------- K2: conv pipeline, one block per node, 64 threads ----------------
// conv1 operands accessed at maximum width:
//   pe rows: 7x LDS.128 (pes padded to 14 ulls/row; 14th read-unused)
//   po rows: 6x LDS.128 (pof = 24 floats = 12 ulls exactly)
//   weights: 3x LDG.128 (tap-paired ulonglong2)
__global__ void __launch_bounds__(64) k_conv(
        const float* __restrict__ x,
        const float* __restrict__ w0, const float* __restrict__ b0,
        const float* __restrict__ b1, const float* __restrict__ b2) {
    int n = blockIdx.x;
    int f = threadIdx.x;
    __shared__ __align__(16) float xs[LQ];
    __shared__ __align__(16) ull   pes[64][14];
    __shared__ __align__(16) float pof[64][24];
    __shared__ float p1s[64][3];

    for (int i = f; i < LQ; i += 64) xs[i] = x[n * LQ + i];
    float w0r[7];
#pragma unroll
    for (int k = 0; k < 7; k++) w0r[k] = w0[f * 7 + k];
    ull w0d[7];
#pragma unroll
    for (int k = 0; k < 7; k++) w0d[k] = pack2(w0r[k], w0r[k]);
    float b0r = b0[f];
    ull b0d = pack2(b0r, b0r);
    // border zeros (incl. the padding slot so LDS.128 reads defined data)
    pes[f][0] = 0ull;
    pes[f][12] = 0ull;
    pes[f][13] = 0ull;
    pof[f][0] = 0.f;
    pof[f][23] = 0.f;
    __syncthreads();

    // conv0 (k=7) + relu + maxpool7; window-pair f32x2 (outputs t=2jp, 2jp+1)
#pragma unroll 1
    for (int jp = 0; jp < 11; jp++) {
        const float2* xr = reinterpret_cast<const float2*>(&xs[14 * jp]);
        float a[20];
#pragma unroll
        for (int m = 0; m < 10; m++) { float2 t = xr[m]; a[2 * m] = t.x; a[2 * m + 1] = t.y; }
        ull xq[13];
#pragma unroll
        for (int l = 0; l < 13; l++) xq[l] = pack2(a[l], a[l + 7]);
        ull s[7];
#pragma unroll
        for (int u = 0; u < 7; u++) s[u] = b0d;
#pragma unroll
        for (int k = 0; k < 7; k++)
#pragma unroll
            for (int u = 0; u < 7; u++) s[u] = fma2(xq[u + k], w0d[k], s[u]);
        float m0 = -1e30f, m1 = -1e30f;
#pragma unroll
        for (int u = 0; u < 7; u++) {
            float2 v = u2f(s[u]);
            m0 = fmaxf(m0, v.x); m1 = fmaxf(m1, v.y);
        }
        m0 = fmaxf(m0, 0.f);
        m1 = fmaxf(m1, 0.f);
        pes[f][jp + 1] = pack2(m0, m1);
        pof[f][2 * jp + 1] = m0;
        pof[f][2 * jp + 2] = m1;
    }
    __syncthreads();

    // conv1 (k=5, pad 2): wide loads + FFMA2
    float b1r = b1[f];
    ull acc2[11];
#pragma unroll
    for (int j = 0; j < 11; j++) acc2[j] = pack2(b1r, b1r);

#pragma unroll 2
    for (int c = 0; c < 64; c++) {
        ull pe[14];
        const ulonglong2* per = reinterpret_cast<const ulonglong2*>(&pes[c][0]);
#pragma unroll
        for (int m = 0; m < 7; m++) {
            ulonglong2 t = per[m];
            pe[2 * m] = t.x; pe[2 * m + 1] = t.y;
        }
        ull po[12];
        const ulonglong2* pou = reinterpret_cast<const ulonglong2*>(&pof[c][0]);
#pragma unroll
        for (int m = 0; m < 6; m++) {
            ulonglong2 t = pou[m];
            po[2 * m] = t.x; po[2 * m + 1] = t.y;
        }
        const ulonglong2* wq = &d_w1q[c * 3 * 64 + f];
        ulonglong2 wq0 = wq[0];
        ulonglong2 wq1 = wq[64];
        ulonglong2 wq2 = wq[128];
        ull w0u = wq0.x, w1u = wq0.y, w2u = wq1.x, w3u = wq1.y, w4u = wq2.x;
#pragma unroll
        for (int j = 0; j < 11; j++) {
            acc2[j] = fma2(pe[j],     w0u, acc2[j]);
            acc2[j] = fma2(po[j],     w1u, acc2[j]);
            acc2[j] = fma2(pe[j + 1], w2u, acc2[j]);
            acc2[j] = fma2(po[j + 1], w3u, acc2[j]);
            acc2[j] = fma2(pe[j + 2], w4u, acc2[j]);
        }
    }
    float acc[22];
#pragma unroll
    for (int j = 0; j < 11; j++) {
        float2 v = u2f(acc2[j]);
        acc[2 * j] = v.x; acc[2 * j + 1] = v.y;
    }
#pragma unroll
    for (int j = 0; j < 3; j++) {
        float m = acc[7 * j];
#pragma unroll
        for (int u = 1; u < 7; u++) m = fmaxf(m, acc[7 * j + u]);
        p1s[f][j] = fmaxf(m, 0.f);
    }
    __syncthreads();

    // conv2 (k=3, len 3 -> 1)
    float s = b2[f];
#pragma unroll 1
    for (int c = 0; c < 64; c++) {
#pragma unroll
        for (int k = 0; k < 3; k++) s = fmaf(p1s[c][k], d_w2t[(c * 3 + k) * 64 + f], s);
    }
    d_H0[n * NF + f] = s;
}

// ---------------- BN1 stats ----------------
__global__ void __launch_bounds__(256) k_bns1a() {
    int t = threadIdx.x;
    int c = t & 63;
    int grp = t >> 6;
    int gid = blockIdx.x * 4 + grp;
    float s = 0.f, q = 0.f;
    for (int n = gid; n < NNODE; n += 244) {
        float v = d_H0[n * NF + c];
        s += v; q += v * v;
    }
    __shared__ float ss[256], sq[256];
    ss[t] = s; sq[t] = q;
    __syncthreads();
    if (t < 64) {
        d_bp1s[blockIdx.x * 64 + t] = ss[t] + ss[64 + t] + ss[128 + t] + ss[192 + t];
        d_bp1q[blockIdx.x * 64 + t] = sq[t] + sq[64 + t] + sq[128 + t] + sq[192 + t];
    }
}
__global__ void __launch_bounds__(64) k_bns1b(const float* __restrict__ gg,
                                              const float* __restrict__ bb) {
    int c = threadIdx.x;
    float s = 0.f, q = 0.f;
    for (int b = 0; b < 61; b++) { s += d_bp1s[b * 64 + c]; q += d_bp1q[b * 64 + c]; }
    float mean = s / (float)NNODE;
    float var = q / (float)NNODE - mean * mean;
    float rs = rsqrtf(var + 1e-5f);
    d_sc1[c] = gg[c] * rs;
    d_sh1[c] = bb[c] - mean * gg[c] * rs;
}
__global__ void __launch_bounds__(128) k_bns2b(const float* __restrict__ gg,
                                               const float* __restrict__ bb) {
    int c = threadIdx.x;
    float s = 0.f, q = 0.f;
    for (int g = 0; g < 2 * NB; g++) { s += d_bp2s[g * HC + c]; q += d_bp2q[g * HC + c]; }
    float mean = s / (float)NNODE;
    float var = q / (float)NNODE - mean * mean;
    float rs = rsqrtf(var + 1e-5f);
    d_sc2[c] = gg[c] * rs;
    d_sh2[c] = bb[c] - mean * gg[c] * rs;
}

// ---------------- GNN phase A: hw = bn?(h) @ W + b. grid (NB, 2), 128 thr ----------------
template<int K, bool BN, int INSEL, int WSEL>
__global__ void __launch_bounds__(128) k_gnn_a(const float* __restrict__ bias) {
    const float* hin = (INSEL == 0) ? (const float*)d_H0
                     : (INSEL == 1) ? (const float*)d_G1 : (const float*)d_G2;
    const ulonglong2* Wu = (WSEL == 0) ? (const ulonglong2*)d_gw0u
                         : (WSEL == 1) ? (const ulonglong2*)d_gw1u : (const ulonglong2*)d_gw2u;
    int g = blockIdx.x;
    int half = blockIdx.y;
    int n0 = half ? 31 : 0;
    int NR = half ? 30 : 31;
    int j = threadIdx.x;
    __shared__ __align__(16) float hs[31 * K];

    for (int idx = j; idx < NR * K; idx += 128) {
        float v = hin[(g * 61 + n0) * K + idx];
        if (BN) { int c = idx & (K - 1); v = fmaf(v, d_sc1[c], d_sh1[c]); }
        hs[idx] = v;
    }
    __syncthreads();

    ull acc[31];
#pragma unroll
    for (int n = 0; n < 31; n++) acc[n] = 0ull;
#pragma unroll 1
    for (int kq = 0; kq < K / 4; kq++) {
        ulonglong2 w = Wu[kq * HC + j];
#pragma unroll
        for (int n = 0; n < 31; n++) {
            ulonglong2 h2 = *reinterpret_cast<const ulonglong2*>(&hs[n * K + 4 * kq]);
            acc[n] = fma2(h2.x, w.x, acc[n]);
            acc[n] = fma2(h2.y, w.y, acc[n]);
        }
    }
    float bj = bias[j];
    for (int n = 0; n < NR; n++) {
        float2 v = u2f(acc[n]);
        d_HW[(g * 61 + n0 + n) * HC + j] = bj + v.x + v.y;
    }
}

// ---------------- GNN phase B: h' = A @ hw. grid (NB, 2), 128 thr ----------------
template<bool RELU, bool STATS, int OUTSEL>
__global__ void __launch_bounds__(128) k_gnn_b() {
    float* hout = (OUTSEL == 1) ? (float*)d_G1 : (float*)d_G2;
    int g = blockIdx.x;
    int half = blockIdx.y;
    int doff = half * 32;
    int ND = half ? 29 : 32;
    int j = threadIdx.x;
    __shared__ __align__(16) float hs[61 * HC];
    __shared__ __align__(16) float As2[61 * 36];

    for (int idx = j; idx < 61 * HC; idx += 128) hs[idx] = d_HW[g * 61 * HC + idx];
    for (int idx = j; idx < 61 * 32; idx += 128) {
        int s = idx >> 5, dd = idx & 31;
        As2[s * 36 + dd] = d_At[g * 4096 + s * 64 + doff + dd];
    }
    __syncthreads();

    ull acc[16];
#pragma unroll
    for (int p = 0; p < 16; p++) acc[p] = 0ull;
#pragma unroll 1
    for (int s = 0; s < 61; s++) {
        float v = hs[s * HC + j];
        ull v2 = pack2(v, v);
        const ulonglong2* ar = reinterpret_cast<const ulonglong2*>(&As2[s * 36]);
#pragma unroll
        for (int p = 0; p < 8; p++) {
            ulonglong2 a = ar[p];
            acc[2 * p]     = fma2(a.x, v2, acc[2 * p]);
            acc[2 * p + 1] = fma2(a.y, v2, acc[2 * p + 1]);
        }
    }
    float ssum = 0.f, sqsum = 0.f;
#pragma unroll
    for (int p = 0; p < 16; p++) {
        float2 r2 = u2f(acc[p]);
        int d0 = 2 * p, d1 = 2 * p + 1;
        if (d0 < ND) {
            float r = r2.x;
            if (STATS) { ssum += r; sqsum += r * r; }
            if (RELU) r = fmaxf(r, 0.f);
            hout[(g * 61 + doff + d0) * HC + j] = r;
        }
        if (d1 < ND) {
            float r = r2.y;
            if (STATS) { ssum += r; sqsum += r * r; }
            if (RELU) r = fmaxf(r, 0.f);
            hout[(g * 61 + doff + d1) * HC + j] = r;
        }
    }
    if (STATS) {
        d_bp2s[(g * 2 + half) * HC + j] = ssum;
        d_bp2q[(g * 2 + half) * HC + j] = sqsum;
    }
}

// ---------------- lin0: split-K over nodes. grid (61, 8), 128 thr ----------------
__global__ void __launch_bounds__(128) k_lin0(const float* __restrict__ W0) {
    int node = blockIdx.x;
    int gc = blockIdx.y;
    int j = threadIdx.x;
    __shared__ __align__(16) float vsT[HC * 20];
    float sc = d_sc2[j], sh = d_sh2[j];
#pragma unroll 1
    for (int q = 0; q < 16; q++) {
        int g = gc * 16 + q;
        vsT[j * 20 + q] = fmaf(d_G1[(g * 61 + node) * HC + j], sc, sh);
    }
    __syncthreads();
    ull acc[8];
#pragma unroll
    for (int p = 0; p < 8; p++) acc[p] = 0ull;
#pragma unroll 1
    for (int ch = 0; ch < HC; ch++) {
        float w = W0[(node * HC + ch) * HC + j];
        ull wd = pack2(w, w);
        const ulonglong2* vr = reinterpret_cast<const ulonglong2*>(&vsT[ch * 20]);
#pragma unroll
        for (int p = 0; p < 4; p++) {
            ulonglong2 v = vr[p];
            acc[2 * p]     = fma2(v.x, wd, acc[2 * p]);
            acc[2 * p + 1] = fma2(v.y, wd, acc[2 * p + 1]);
        }
    }
#pragma unroll
    for (int p = 0; p < 8; p++) {
        float2 v = u2f(acc[p]);
        int g0 = gc * 16 + 2 * p;
        d_P[(g0 * NPG + node) * HC + j] = v.x;
        d_P[((g0 + 1) * NPG + node) * HC + j] = v.y;
    }
}

// ---------------- head ----------------
__global__ void __launch_bounds__(128) k_head(const float* __restrict__ b0,
                                              const float* __restrict__ W1,
                                              const float* __restrict__ b1,
                                              const float* __restrict__ W2,
                                              const float* __restrict__ b2,
                                              float* __restrict__ out) {
    int g = blockIdx.x;
    int j = threadIdx.x;
    float z = b0[j];
    for (int node = 0; node < NPG; node++) z += d_P[(g * NPG + node) * HC + j];
    z = fmaxf(z, 0.f);
    __shared__ float z1[HC];
    z1[j] = z;
    __syncthreads();
    float a = b1[j];
    for (int k = 0; k < HC; k++) a = fmaf(z1[k], W1[k * HC + j], a);
    a = fmaxf(a, 0.f);
    __shared__ float z2[HC];
    z2[j] = a;
    __syncthreads();
    __shared__ float z3[4];
    if (j < 4) {
        float s = b2[j];
        for (int k = 0; k < HC; k++) s = fmaf(z2[k], W2[k * 4 + j], s);
        z3[j] = s;
    }
    __syncthreads();
    if (j == 0) {
        float m = fmaxf(fmaxf(z3[0], z3[1]), fmaxf(z3[2], z3[3]));
        float se = 0.f;
        for (int i = 0; i < 4; i++) se += expf(z3[i] - m);
        float l = logf(se);
        for (int i = 0; i < 4; i++) out[g * 4 + i] = z3[i] - m - l;
    }
}

// ---------------- launch ----------------
extern "C" void kernel_launch(void* const* d_in, const int* in_sizes, int n_in,
                              void* d_out, int out_size) {
    const float* x    = (const float*)d_in[0];
    const int*   ei   = (const int*)d_in[1];
    const float* ef   = (const float*)d_in[3];
    const float* cw0  = (const float*)d_in[4];
    const float* cb0  = (const float*)d_in[5];
    const float* cw1  = (const float*)d_in[6];
    const float* cb1  = (const float*)d_in[7];
    const float* cw2  = (const float*)d_in[8];
    const float* cb2  = (const float*)d_in[9];
    const float* bn1g = (const float*)d_in[10];
    const float* bn1b = (const float*)d_in[11];
    const float* gw0  = (const float*)d_in[12];
    const float* gb0  = (const float*)d_in[13];
    const float* gw1  = (const float*)d_in[14];
    const float* gb1  = (const float*)d_in[15];
    const float* gw2  = (const float*)d_in[16];
    const float* gb2  = (const float*)d_in[17];
    const float* bn2g = (const float*)d_in[18];
    const float* bn2b = (const float*)d_in[19];
    const float* lw0  = (const float*)d_in[20];
    const float* lb0  = (const float*)d_in[21];
    const float* lw1  = (const float*)d_in[22];
    const float* lb1  = (const float*)d_in[23];
    const float* lw2  = (const float*)d_in[24];
    const float* lb2  = (const float*)d_in[25];
    const float* eww  = (const float*)d_in[26];
    const float* ewb  = (const float*)d_in[27];
    float* out = (float*)d_out;

    // Launch order arranged so k_conv is launch #4 (ncu capture slot).
    k_prep_zero<<<256, 256>>>();
    k_prep_w<<<256, 256>>>(cw1, cw2, gw0, gw1, gw2);
    dim3 eg((EPG + 31) / 32, NB / 32);
    k_edges<<<eg, 1024>>>(ef, ei, eww, ewb, out);
    k_conv<<<NNODE, 64>>>(x, cw0, cb0, cb1, cb2);
    k_bns1a<<<61, 256>>>();
    k_bns1b<<<1, 64>>>(bn1g, bn1b);
    dim3 gg(NB, 2);
    k_gnn_a< 64, true,  0, 0><<<gg, 128>>>(gb0);
    k_gnn_b<true,  false, 1><<<gg, 128>>>();
    k_gnn_a<128, false, 1, 1><<<gg, 128>>>(gb1);
    k_gnn_b<true,  false, 2><<<gg, 128>>>();
    k_gnn_a<128, false, 2, 2><<<gg, 128>>>(gb2);
    k_gnn_b<false, true,  1><<<gg, 128>>>();
    k_bns2b<<<1, 128>>>(bn2g, bn2b);
    dim3 lg(NPG, 8);
    k_lin0<<<lg, 128>>>(lw0);
    k_head<<<NB, 128>>>(lb0, lw1, lb1, lw2, lb2, out);
}

// round 13
// speedup vs baseline: 1.0751x; 1.0751x over previous
#include <cuda_runtime.h>

// Problem constants
#define NPG   61
#define NB    128
#define NNODE 7808         // NB*NPG
#define NE    468480       // NB * 61*60
#define EPG   3660
#define LQ    160
#define NF    64
#define HC    128

typedef unsigned long long ull;

// ---------------- f32x2 helpers ----------------
__device__ __forceinline__ ull pack2(float lo, float hi) {
    ull r; asm("mov.b64 %0, {%1, %2};" : "=l"(r) : "f"(lo), "f"(hi)); return r;
}
__device__ __forceinline__ float2 u2f(ull u) {
    float2 v; asm("mov.b64 {%0, %1}, %2;" : "=f"(v.x), "=f"(v.y) : "l"(u)); return v;
}
__device__ __forceinline__ ull fma2(ull a, ull b, ull c) {
    ull d; asm("fma.rn.f32x2 %0, %1, %2, %3;" : "=l"(d) : "l"(a), "l"(b), "l"(c)); return d;
}

// ---------------- device scratch ----------------
__device__ float      d_At[NB * 64 * 64];     // TRANSPOSED adjacency At[g][s][d]
__device__ float      d_w1t[64 * 5 * 64];     // conv1 weights transposed [(c*5+k)*64+f]
__device__ float      d_w2t[64 * 3 * 64];     // conv2 weights transposed
__device__ ulonglong2 d_gw0u[16 * HC];
__device__ ulonglong2 d_gw1u[32 * HC];
__device__ ulonglong2 d_gw2u[32 * HC];
__device__ float      d_H0[NNODE * NF];
__device__ float      d_G1[NNODE * HC];
__device__ float      d_G2[NNODE * HC];
__device__ float      d_P[NB * NPG * HC];     // lin0 partials, [g][node][j]
__device__ float      d_bp1s[61 * NF], d_bp1q[61 * NF];
__device__ float      d_bp2s[2 * NB * HC], d_bp2q[2 * NB * HC];
__device__ float      d_sc1[NF], d_sh1[NF];
__device__ float      d_sc2[HC], d_sh2[HC];

// ---------------- K0a: zero adjacency ----------------
__global__ void k_prep_zero() {
    int t0 = blockIdx.x * blockDim.x + threadIdx.x;
    int stride = gridDim.x * blockDim.x;
    for (int i = t0; i < NB * 64 * 64; i += stride) d_At[i] = 0.f;
}

// ---------------- K0b: transpose/pack weights ----------------
__global__ void k_prep_w(const float* __restrict__ w1, const float* __restrict__ w2,
                         const float* __restrict__ gw0, const float* __restrict__ gw1,
                         const float* __restrict__ gw2) {
    int t0 = blockIdx.x * blockDim.x + threadIdx.x;
    int stride = gridDim.x * blockDim.x;
    for (int i = t0; i < 64 * 5 * 64; i += stride) {
        int f = i & 63; int r = i >> 6; int k = r % 5; int c = r / 5;
        d_w1t[i] = w1[(f * 64 + c) * 5 + k];
    }
    for (int i = t0; i < 64 * 3 * 64; i += stride) {
        int f = i & 63; int r = i >> 6; int k = r % 3; int c = r / 3;
        d_w2t[i] = w2[(f * 64 + c) * 3 + k];
    }
    for (int i = t0; i < 16 * HC; i += stride) {
        int j = i & (HC - 1); int kq = i >> 7;
        ulonglong2 u;
        u.x = pack2(gw0[(4 * kq) * HC + j], gw0[(4 * kq + 1) * HC + j]);
        u.y = pack2(gw0[(4 * kq + 2) * HC + j], gw0[(4 * kq + 3) * HC + j]);
        d_gw0u[i] = u;
    }
    for (int i = t0; i < 32 * HC; i += stride) {
        int j = i & (HC - 1); int kq = i >> 7;
        ulonglong2 u, v;
        u.x = pack2(gw1[(4 * kq) * HC + j], gw1[(4 * kq + 1) * HC + j]);
        u.y = pack2(gw1[(4 * kq + 2) * HC + j], gw1[(4 * kq + 3) * HC + j]);
        d_gw1u[i] = u;
        v.x = pack2(gw2[(4 * kq) * HC + j], gw2[(4 * kq + 1) * HC + j]);
        v.y = pack2(gw2[(4 * kq + 2) * HC + j], gw2[(4 * kq + 3) * HC + j]);
        d_gw2u[i] = v;
    }
}

// ---------------- K1: edges ----------------
__global__ void __launch_bounds__(1024) k_edges(
        const float* __restrict__ ef, const int* __restrict__ ei,
        const float* __restrict__ eww, const float* __restrict__ ewb,
        float* __restrict__ out) {
    int w = threadIdx.x >> 5;
    int l = threadIdx.x & 31;
    int i0 = blockIdx.x * 32;
    int g0 = blockIdx.y * 32;
    __shared__ float ts[32][33];

    int g = g0 + w;
    int i = i0 + l;
    float v = 0.f;
    if (i < EPG) {
        int e = g * EPG + i;
        v = tanhf(fmaf(ef[e * 3 + 0], eww[0],
                 fmaf(ef[e * 3 + 1], eww[1],
                 fmaf(ef[e * 3 + 2], eww[2], ewb[0]))));
        int s = ei[e];
        int d = ei[NE + e];
        int g2 = d / NPG;
        int dl = d - g2 * NPG;
        int sl = s - g2 * NPG;
        d_At[(g2 * 64 + sl) * 64 + dl] = v;
    }
    ts[w][l] = v;
    __syncthreads();
    int iw = i0 + w;
    if (iw < EPG) out[NB * 4 + iw * NB + g0 + l] = ts[l][w];
}

// ---------------- K2: conv pipeline, one block per node, 64 threads ----------------
// pe rows: 7x LDS.128; po rows: 6x LDS.128; weights: 5x scalar LDG.32 (1 wavefront each,
// f-contiguous) + 5 dup-pack MOVs — minimizes L1 wavefront pressure.
__global__ void __launch_bounds__(64) k_conv(
        const float* __restrict__ x,
        const float* __restrict__ w0, const float* __restrict__ b0,
        const float* __restrict__ b1, const float* __restrict__ b2) {
    int n = blockIdx.x;
    int f = threadIdx.x;
    __shared__ __align__(16) float xs[LQ];
    __shared__ __align__(16) ull   pes[64][14];
    __shared__ __align__(16) float pof[64][24];
    __shared__ float p1s[64][3];

    for (int i = f; i < LQ; i += 64) xs[i] = x[n * LQ + i];
    float w0r[7];
#pragma unroll
    for (int k = 0; k < 7; k++) w0r[k] = w0[f * 7 + k];
    ull w0d[7];
#pragma unroll
    for (int k = 0; k < 7; k++) w0d[k] = pack2(w0r[k], w0r[k]);
    float b0r = b0[f];
    ull b0d = pack2(b0r, b0r);
    // border zeros (incl. the padding slot so LDS.128 reads defined data)
    pes[f][0] = 0ull;
    pes[f][12] = 0ull;
    pes[f][13] = 0ull;
    pof[f][0] = 0.f;
    pof[f][23] = 0.f;
    __syncthreads();

    // conv0 (k=7) + relu + maxpool7; window-pair f32x2 (outputs t=2jp, 2jp+1)
#pragma unroll 1
    for (int jp = 0; jp < 11; jp++) {
        const float2* xr = reinterpret_cast<const float2*>(&xs[14 * jp]);
        float a[20];
#pragma unroll
        for (int m = 0; m < 10; m++) { float2 t = xr[m]; a[2 * m] = t.x; a[2 * m + 1] = t.y; }
        ull xq[13];
#pragma unroll
        for (int l = 0; l < 13; l++) xq[l] = pack2(a[l], a[l + 7]);
        ull s[7];
#pragma unroll
        for (int u = 0; u < 7; u++) s[u] = b0d;
#pragma unroll
        for (int k = 0; k < 7; k++)
#pragma unroll
            for (int u = 0; u < 7; u++) s[u] = fma2(xq[u + k], w0d[k], s[u]);
        float m0 = -1e30f, m1 = -1e30f;
#pragma unroll
        for (int u = 0; u < 7; u++) {
            float2 v = u2f(s[u]);
            m0 = fmaxf(m0, v.x); m1 = fmaxf(m1, v.y);
        }
        m0 = fmaxf(m0, 0.f);
        m1 = fmaxf(m1, 0.f);
        pes[f][jp + 1] = pack2(m0, m1);
        pof[f][2 * jp + 1] = m0;
        pof[f][2 * jp + 2] = m1;
    }
    __syncthreads();

    // conv1 (k=5, pad 2): wide LDS + scalar weight LDG + FFMA2
    float b1r = b1[f];
    ull acc2[11];
#pragma unroll
    for (int j = 0; j < 11; j++) acc2[j] = pack2(b1r, b1r);

#pragma unroll 2
    for (int c = 0; c < 64; c++) {
        ull pe[14];
        const ulonglong2* per = reinterpret_cast<const ulonglong2*>(&pes[c][0]);
#pragma unroll
        for (int m = 0; m < 7; m++) {
            ulonglong2 t = per[m];
            pe[2 * m] = t.x; pe[2 * m + 1] = t.y;
        }
        ull po[12];
        const ulonglong2* pou = reinterpret_cast<const ulonglong2*>(&pof[c][0]);
#pragma unroll
        for (int m = 0; m < 6; m++) {
            ulonglong2 t = pou[m];
            po[2 * m] = t.x; po[2 * m + 1] = t.y;
        }
        const float* wp = &d_w1t[c * 5 * 64 + f];
        float wa = wp[0], wb = wp[64], wc = wp[128], wd = wp[192], we = wp[256];
        ull w0u = pack2(wa, wa);
        ull w1u = pack2(wb, wb);
        ull w2u = pack2(wc, wc);
        ull w3u = pack2(wd, wd);
        ull w4u = pack2(we, we);
#pragma unroll
        for (int j = 0; j < 11; j++) {
            acc2[j] = fma2(pe[j],     w0u, acc2[j]);
            acc2[j] = fma2(po[j],     w1u, acc2[j]);
            acc2[j] = fma2(pe[j + 1], w2u, acc2[j]);
            acc2[j] = fma2(po[j + 1], w3u, acc2[j]);
            acc2[j] = fma2(pe[j + 2], w4u, acc2[j]);
        }
    }
    float acc[22];
#pragma unroll
    for (int j = 0; j < 11; j++) {
        float2 v = u2f(acc2[j]);
        acc[2 * j] = v.x; acc[2 * j + 1] = v.y;
    }
#pragma unroll
    for (int j = 0; j < 3; j++) {
        float m = acc[7 * j];
#pragma unroll
        for (int u = 1; u < 7; u++) m = fmaxf(m, acc[7 * j + u]);
        p1s[f][j] = fmaxf(m, 0.f);
    }
    __syncthreads();

    // conv2 (k=3, len 3 -> 1)
    float s = b2[f];
#pragma unroll 1
    for (int c = 0; c < 64; c++) {
#pragma unroll
        for (int k = 0; k < 3; k++) s = fmaf(p1s[c][k], d_w2t[(c * 3 + k) * 64 + f], s);
    }
    d_H0[n * NF + f] = s;
}

// ---------------- BN1 stats ----------------
__global__ void __launch_bounds__(256) k_bns1a() {
    int t = threadIdx.x;
    int c = t & 63;
    int grp = t >> 6;
    int gid = blockIdx.x * 4 + grp;
    float s = 0.f, q = 0.f;
    for (int n = gid; n < NNODE; n += 244) {
        float v = d_H0[n * NF + c];
        s += v; q += v * v;
    }
    __shared__ float ss[256], sq[256];
    ss[t] = s; sq[t] = q;
    __syncthreads();
    if (t < 64) {
        d_bp1s[blockIdx.x * 64 + t] = ss[t] + ss[64 + t] + ss[128 + t] + ss[192 + t];
        d_bp1q[blockIdx.x * 64 + t] = sq[t] + sq[64 + t] + sq[128 + t] + sq[192 + t];
    }
}
__global__ void __launch_bounds__(64) k_bns1b(const float* __restrict__ gg,
                                              const float* __restrict__ bb) {
    int c = threadIdx.x;
    float s = 0.f, q = 0.f;
    for (int b = 0; b < 61; b++) { s += d_bp1s[b * 64 + c]; q += d_bp1q[b * 64 + c]; }
    float mean = s / (float)NNODE;
    float var = q / (float)NNODE - mean * mean;
    float rs = rsqrtf(var + 1e-5f);
    d_sc1[c] = gg[c] * rs;
    d_sh1[c] = bb[c] - mean * gg[c] * rs;
}
__global__ void __launch_bounds__(128) k_bns2b(const float* __restrict__ gg,
                                               const float* __restrict__ bb) {
    int c = threadIdx.x;
    float s = 0.f, q = 0.f;
    for (int g = 0; g < 2 * NB; g++) { s += d_bp2s[g * HC + c]; q += d_bp2q[g * HC + c]; }
    float mean = s / (float)NNODE;
    float var = q / (float)NNODE - mean * mean;
    float rs = rsqrtf(var + 1e-5f);
    d_sc2[c] = gg[c] * rs;
    d_sh2[c] = bb[c] - mean * gg[c] * rs;
}

// ---------------- Fused GNN layer: grid NB, 256 threads ----------------
// Thread = (j = tid&127, half = tid>>7). Phase A: hw = bn?(h) @ W + b for this
// half's node rows (31/30), staged entirely in smem. Phase B: h' = A @ hw for
// this half's d rows (32/29). One kernel per layer, no global hw round-trip.
template<int K, bool BN, bool STATS, int INSEL, int OUTSEL, bool RELU, int WSEL>
__global__ void __launch_bounds__(256) k_gnn(const float* __restrict__ bias) {
    const float* hin = (INSEL == 0) ? (const float*)d_H0
                     : (INSEL == 1) ? (const float*)d_G1 : (const float*)d_G2;
    float* hout = (OUTSEL == 1) ? (float*)d_G1 : (float*)d_G2;
    const ulonglong2* Wu = (WSEL == 0) ? (const ulonglong2*)d_gw0u
                         : (WSEL == 1) ? (const ulonglong2*)d_gw1u : (const ulonglong2*)d_gw2u;
    int g = blockIdx.x;
    int tid = threadIdx.x;
    int j = tid & 127;
    int half = tid >> 7;
    __shared__ __align__(16) float hs[61 * HC];    // input h (61xK), then hw (61x128)
    __shared__ __align__(16) float As2[61 * 68];   // A[s][d], padded stride 68

    for (int idx = tid; idx < 61 * K; idx += 256) {
        float v = hin[g * 61 * K + idx];
        if (BN) { int c = idx & (K - 1); v = fmaf(v, d_sc1[c], d_sh1[c]); }
        hs[idx] = v;
    }
    for (int idx = tid; idx < 61 * 64; idx += 256) {
        int s = idx >> 6, dd = idx & 63;
        As2[s * 68 + dd] = d_At[g * 4096 + idx];
    }
    __syncthreads();

    // Phase A: rows n0..n0+NR-1
    int n0 = half ? 31 : 0;
    int NR = half ? 30 : 31;
    ull acc[31];
#pragma unroll
    for (int n = 0; n < 31; n++) acc[n] = 0ull;
#pragma unroll 1
    for (int kq = 0; kq < K / 4; kq++) {
        ulonglong2 w = Wu[kq * HC + j];
#pragma unroll
        for (int n = 0; n < 31; n++) {
            int row = n0 + n;
            if (row > 60) row = 60;           // half1 n=30 dup (discarded)
            ulonglong2 h2 = *reinterpret_cast<const ulonglong2*>(&hs[row * K + 4 * kq]);
            acc[n] = fma2(h2.x, w.x, acc[n]);
            acc[n] = fma2(h2.y, w.y, acc[n]);
        }
    }
    float hwr[31];
    float bj = bias[j];
#pragma unroll
    for (int n = 0; n < 31; n++) { float2 v = u2f(acc[n]); hwr[n] = bj + v.x + v.y; }
    __syncthreads();                          // all hs reads done
    for (int n = 0; n < NR; n++) hs[(n0 + n) * HC + j] = hwr[n];
    __syncthreads();

    // Phase B: d rows doff..doff+ND-1
    int doff = half * 32;
    int ND = half ? 29 : 32;
    ull acc2[16];
#pragma unroll
    for (int p = 0; p < 16; p++) acc2[p] = 0ull;
#pragma unroll 1
    for (int s = 0; s < 61; s++) {
        float v = hs[s * HC + j];
        ull v2 = pack2(v, v);
        const ulonglong2* ar = reinterpret_cast<const ulonglong2*>(&As2[s * 68 + doff]);
#pragma unroll
        for (int p = 0; p < 8; p++) {
            ulonglong2 a = ar[p];
            acc2[2 * p]     = fma2(a.x, v2, acc2[2 * p]);
            acc2[2 * p + 1] = fma2(a.y, v2, acc2[2 * p + 1]);
        }
    }
    float ssum = 0.f, sqsum = 0.f;
#pragma unroll
    for (int p = 0; p < 16; p++) {
        float2 r2 = u2f(acc2[p]);
        int d0 = 2 * p, d1 = 2 * p + 1;
        if (d0 < ND) {
            float r = r2.x;
            if (STATS) { ssum += r; sqsum += r * r; }
            if (RELU) r = fmaxf(r, 0.f);
            hout[(g * 61 + doff + d0) * HC + j] = r;
        }
        if (d1 < ND) {
            float r = r2.y;
            if (STATS) { ssum += r; sqsum += r * r; }
            if (RELU) r = fmaxf(r, 0.f);
            hout[(g * 61 + doff + d1) * HC + j] = r;
        }
    }
    if (STATS) {
        d_bp2s[(g * 2 + half) * HC + j] = ssum;
        d_bp2q[(g * 2 + half) * HC + j] = sqsum;
    }
}

// ---------------- lin0: split-K over nodes. grid (61, 8), 128 thr ----------------
__global__ void __launch_bounds__(128) k_lin0(const float* __restrict__ W0) {
    int node = blockIdx.x;
    int gc = blockIdx.y;
    int j = threadIdx.x;
    __shared__ __align__(16) float vsT[HC * 20];
    float sc = d_sc2[j], sh = d_sh2[j];
#pragma unroll 1
    for (int q = 0; q < 16; q++) {
        int g = gc * 16 + q;
        vsT[j * 20 + q] = fmaf(d_G1[(g * 61 + node) * HC + j], sc, sh);
    }
    __syncthreads();
    ull acc[8];
#pragma unroll
    for (int p = 0; p < 8; p++) acc[p] = 0ull;
#pragma unroll 1
    for (int ch = 0; ch < HC; ch++) {
        float w = W0[(node * HC + ch) * HC + j];
        ull wd = pack2(w, w);
        const ulonglong2* vr = reinterpret_cast<const ulonglong2*>(&vsT[ch * 20]);
#pragma unroll
        for (int p = 0; p < 4; p++) {
            ulonglong2 v = vr[p];
            acc[2 * p]     = fma2(v.x, wd, acc[2 * p]);
            acc[2 * p + 1] = fma2(v.y, wd, acc[2 * p + 1]);
        }
    }
#pragma unroll
    for (int p = 0; p < 8; p++) {
        float2 v = u2f(acc[p]);
        int g0 = gc * 16 + 2 * p;
        d_P[(g0 * NPG + node) * HC + j] = v.x;
        d_P[((g0 + 1) * NPG + node) * HC + j] = v.y;
    }
}

// ---------------- head ----------------
__global__ void __launch_bounds__(128) k_head(const float* __restrict__ b0,
                                              const float* __restrict__ W1,
                                              const float* __restrict__ b1,
                                              const float* __restrict__ W2,
                                              const float* __restrict__ b2,
                                              float* __restrict__ out) {
    int g = blockIdx.x;
    int j = threadIdx.x;
    float z = b0[j];
    for (int node = 0; node < NPG; node++) z += d_P[(g * NPG + node) * HC + j];
    z = fmaxf(z, 0.f);
    __shared__ float z1[HC];
    z1[j] = z;
    __syncthreads();
    float a = b1[j];
    for (int k = 0; k < HC; k++) a = fmaf(z1[k], W1[k * HC + j], a);
    a = fmaxf(a, 0.f);
    __shared__ float z2[HC];
    z2[j] = a;
    __syncthreads();
    __shared__ float z3[4];
    if (j < 4) {
        float s = b2[j];
        for (int k = 0; k < HC; k++) s = fmaf(z2[k], W2[k * 4 + j], s);
        z3[j] = s;
    }
    __syncthreads();
    if (j == 0) {
        float m = fmaxf(fmaxf(z3[0], z3[1]), fmaxf(z3[2], z3[3]));
        float se = 0.f;
        for (int i = 0; i < 4; i++) se += expf(z3[i] - m);
        float l = logf(se);
        for (int i = 0; i < 4; i++) out[g * 4 + i] = z3[i] - m - l;
    }
}

// ---------------- launch ----------------
extern "C" void kernel_launch(void* const* d_in, const int* in_sizes, int n_in,
                              void* d_out, int out_size) {
    const float* x    = (const float*)d_in[0];
    const int*   ei   = (const int*)d_in[1];
    const float* ef   = (const float*)d_in[3];
    const float* cw0  = (const float*)d_in[4];
    const float* cb0  = (const float*)d_in[5];
    const float* cw1  = (const float*)d_in[6];
    const float* cb1  = (const float*)d_in[7];
    const float* cw2  = (const float*)d_in[8];
    const float* cb2  = (const float*)d_in[9];
    const float* bn1g = (const float*)d_in[10];
    const float* bn1b = (const float*)d_in[11];
    const float* gw0  = (const float*)d_in[12];
    const float* gb0  = (const float*)d_in[13];
    const float* gw1  = (const float*)d_in[14];
    const float* gb1  = (const float*)d_in[15];
    const float* gw2  = (const float*)d_in[16];
    const float* gb2  = (const float*)d_in[17];
    const float* bn2g = (const float*)d_in[18];
    const float* bn2b = (const float*)d_in[19];
    const float* lw0  = (const float*)d_in[20];
    const float* lb0  = (const float*)d_in[21];
    const float* lw1  = (const float*)d_in[22];
    const float* lb1  = (const float*)d_in[23];
    const float* lw2  = (const float*)d_in[24];
    const float* lb2  = (const float*)d_in[25];
    const float* eww  = (const float*)d_in[26];
    const float* ewb  = (const float*)d_in[27];
    float* out = (float*)d_out;

    // Launch order keeps k_conv at launch #4 (ncu capture slot).
    k_prep_zero<<<256, 256>>>();
    k_prep_w<<<256, 256>>>(cw1, cw2, gw0, gw1, gw2);
    dim3 eg((EPG + 31) / 32, NB / 32);
    k_edges<<<eg, 1024>>>(ef, ei, eww, ewb, out);
    k_conv<<<NNODE, 64>>>(x, cw0, cb0, cb1, cb2);
    k_bns1a<<<61, 256>>>();
    k_bns1b<<<1, 64>>>(bn1g, bn1b);
    k_gnn< 64, true,  false, 0, 1, true,  0><<<NB, 256>>>(gb0);
    k_gnn<128, false, false, 1, 2, true,  1><<<NB, 256>>>(gb1);
    k_gnn<128, false, true,  2, 1, false, 2><<<NB, 256>>>(gb2);
    k_bns2b<<<1, 128>>>(bn2g, bn2b);
    dim3 lg(NPG, 8);
    k_lin0<<<lg, 128>>>(lw0);
    k_head<<<NB, 128>>>(lb0, lw1, lb1, lw2, lb2, out);
}